// round 2
// baseline (speedup 1.0000x reference)
#include <cuda_runtime.h>
#include <cstdint>

#define Ddim 128
#define Tdim 1024
#define Bdim 128
#define CH3 (3 * Ddim)
#define NCHUNK 4
#define TCHUNK (Tdim / NCHUNK)
#define ROWS_PER_BLOCK 64
#define NWARPS 8

// Scratch for per-(b,chunk,d) partial sums of y over T.
__device__ float g_partial[Bdim * NCHUNK * Ddim];

// ---------------------------------------------------------------------------
// Pass 1: partial column sums of y = x[:, :, :D] over T chunks.
// grid (B, NCHUNK), block 128 threads (one per d). Coalesced 512B per step.
// ---------------------------------------------------------------------------
__global__ void mean_partial_kernel(const float* __restrict__ x) {
    const int b = blockIdx.x;
    const int c = blockIdx.y;
    const int d = threadIdx.x;
    const float* p = x + ((size_t)b * Tdim + (size_t)c * TCHUNK) * CH3 + d;
    float s0 = 0.f, s1 = 0.f, s2 = 0.f, s3 = 0.f;
#pragma unroll 4
    for (int t = 0; t < TCHUNK; t += 4) {
        s0 += p[(size_t)(t + 0) * CH3];
        s1 += p[(size_t)(t + 1) * CH3];
        s2 += p[(size_t)(t + 2) * CH3];
        s3 += p[(size_t)(t + 3) * CH3];
    }
    g_partial[(b * NCHUNK + c) * Ddim + d] = (s0 + s1) + (s2 + s3);
}

// ---------------------------------------------------------------------------
// Pass 2: fused exp / softmax / mean-subtract / matvec / outputs.
// One warp per (b,t) row. Block = 8 warps, 64 rows (8 iterations).
// K (128x128 fp32) staged in shared; matvec uses packed fma.rn.f32x2.
// ---------------------------------------------------------------------------
__global__ void __launch_bounds__(256, 3)
cci_main_kernel(const float* __restrict__ x,
                const float* __restrict__ kmat,
                float* __restrict__ out) {
    extern __shared__ float smem[];
    float* Ks = smem;                       // 128*128 floats
    float* means = Ks + Ddim * Ddim;        // 128 floats
    float* vbuf = means + Ddim;             // NWARPS * 128 floats

    const int tid = threadIdx.x;
    const int w = tid >> 5;
    const int lane = tid & 31;

    // Stage kernel matrix into shared (float4-coalesced).
    {
        const float4* src = (const float4*)kmat;
        float4* dst = (float4*)Ks;
#pragma unroll
        for (int i = tid; i < (Ddim * Ddim) / 4; i += 256) dst[i] = src[i];
    }

    const int row0 = blockIdx.x * ROWS_PER_BLOCK;
    const int b = row0 / Tdim;   // 64 | 1024, so whole block shares one b

    // Finalize mean for this b.
    if (tid < Ddim) {
        float m = 0.f;
#pragma unroll
        for (int c = 0; c < NCHUNK; ++c) m += g_partial[(b * NCHUNK + c) * Ddim + tid];
        means[tid] = m * (1.0f / Tdim);
    }
    __syncthreads();

    float* vrow = vbuf + w * Ddim;
    const float4 mn = *(const float4*)(means + 4 * lane);

#pragma unroll 1
    for (int it = 0; it < ROWS_PER_BLOCK / NWARPS; ++it) {
        const int row = row0 + it * NWARPS + w;
        const float* xr = x + (size_t)row * CH3;
        float* outr = out + (size_t)row * CH3;

        const float4 y  = *(const float4*)(xr + 4 * lane);
        const float4 wv = *(const float4*)(xr + Ddim + 4 * lane);
        const float4 yo = *(const float4*)(xr + 2 * Ddim + 4 * lane);

        // intensity = exp(w); also the softmax numerator.
        float4 inten;
        inten.x = __expf(wv.x);
        inten.y = __expf(wv.y);
        inten.z = __expf(wv.z);
        inten.w = __expf(wv.w);
        *(float4*)(outr + Ddim + 4 * lane) = inten;

        // softmax denominator across the 128 channels (warp reduce).
        float s = (inten.x + inten.y) + (inten.z + inten.w);
#pragma unroll
        for (int off = 16; off; off >>= 1)
            s += __shfl_xor_sync(0xffffffffu, s, off);
        const float rs = 1.0f / s;

        // v = softmax(w) * (y - mean), staged to smem for broadcast reads.
        float4 v;
        v.x = inten.x * rs * (y.x - mn.x);
        v.y = inten.y * rs * (y.y - mn.y);
        v.z = inten.z * rs * (y.z - mn.z);
        v.w = inten.w * rs * (y.w - mn.w);
        *(float4*)(vrow + 4 * lane) = v;
        __syncwarp();

        // smooth[c] = sum_j v[j] * K[j][c] + mean[c], lane owns c = 4*lane..+3.
        unsigned long long acc01 = 0ull, acc23 = 0ull;  // packed {f32,f32}
#pragma unroll 4
        for (int j = 0; j < Ddim; j += 4) {
            const float4 vj4 = *(const float4*)(vrow + j);  // broadcast
#pragma unroll
            for (int u = 0; u < 4; ++u) {
                const float vj = (u == 0) ? vj4.x : (u == 1) ? vj4.y : (u == 2) ? vj4.z : vj4.w;
                unsigned long long vv;
                asm("mov.b64 %0, {%1, %1};" : "=l"(vv) : "r"(__float_as_uint(vj)));
                const float4 kk = *(const float4*)(Ks + (j + u) * Ddim + 4 * lane);
                unsigned long long k01, k23;
                asm("mov.b64 %0, {%1, %2};" : "=l"(k01)
                    : "r"(__float_as_uint(kk.x)), "r"(__float_as_uint(kk.y)));
                asm("mov.b64 %0, {%1, %2};" : "=l"(k23)
                    : "r"(__float_as_uint(kk.z)), "r"(__float_as_uint(kk.w)));
                asm("fma.rn.f32x2 %0, %1, %2, %0;" : "+l"(acc01) : "l"(k01), "l"(vv));
                asm("fma.rn.f32x2 %0, %1, %2, %0;" : "+l"(acc23) : "l"(k23), "l"(vv));
            }
        }
        unsigned int u0, u1, u2, u3;
        asm("mov.b64 {%0, %1}, %2;" : "=r"(u0), "=r"(u1) : "l"(acc01));
        asm("mov.b64 {%0, %1}, %2;" : "=r"(u2), "=r"(u3) : "l"(acc23));

        float4 sm4;
        sm4.x = __uint_as_float(u0) + mn.x;
        sm4.y = __uint_as_float(u1) + mn.y;
        sm4.z = __uint_as_float(u2) + mn.z;
        sm4.w = __uint_as_float(u3) + mn.w;
        *(float4*)(outr + 4 * lane) = sm4;

        float4 yt;
        yt.x = yo.x - sm4.x;
        yt.y = yo.y - sm4.y;
        yt.z = yo.z - sm4.z;
        yt.w = yo.w - sm4.w;
        *(float4*)(outr + 2 * Ddim + 4 * lane) = yt;

        __syncwarp();  // vrow reused next iteration
    }
}

// ---------------------------------------------------------------------------
extern "C" void kernel_launch(void* const* d_in, const int* in_sizes, int n_in,
                              void* d_out, int out_size) {
    // Identify inputs by size (x = B*T*3D, kernel = D*D).
    const float* x;
    const float* kmat;
    if (in_sizes[0] == Ddim * Ddim) {
        kmat = (const float*)d_in[0];
        x = (const float*)d_in[1];
    } else {
        x = (const float*)d_in[0];
        kmat = (const float*)d_in[1];
    }
    float* out = (float*)d_out;

    const int smem_bytes = (Ddim * Ddim + Ddim + NWARPS * Ddim) * sizeof(float);
    cudaFuncSetAttribute(cci_main_kernel,
                         cudaFuncAttributeMaxDynamicSharedMemorySize, smem_bytes);

    mean_partial_kernel<<<dim3(Bdim, NCHUNK), Ddim>>>(x);
    cci_main_kernel<<<(Bdim * Tdim) / ROWS_PER_BLOCK, 256, smem_bytes>>>(x, kmat, out);
}

// round 3
// speedup vs baseline: 1.9597x; 1.9597x over previous
#include <cuda_runtime.h>
#include <cstdint>

#define Ddim 128
#define Tdim 1024
#define Bdim 128
#define CH3 (3 * Ddim)
#define NCHUNK 8
#define TCHUNK (Tdim / NCHUNK)
#define NWARPS 8
#define ROWS_PER_WARP 8
#define ROWS_PER_BLOCK (NWARPS * ROWS_PER_WARP)   // 64

typedef unsigned long long ull;

// Scratch for per-(b,chunk,d) partial sums of y over T.
__device__ float g_partial[Bdim * NCHUNK * Ddim];

// ---------------------------------------------------------------------------
// f32x2 packed-FMA helpers
// ---------------------------------------------------------------------------
__device__ __forceinline__ ull dup2(float a) {
    ull r;
    asm("mov.b64 %0, {%1, %1};" : "=l"(r) : "r"(__float_as_uint(a)));
    return r;
}
__device__ __forceinline__ void fma2(ull& acc, ull a, ull b) {
    asm("fma.rn.f32x2 %0, %1, %2, %0;" : "+l"(acc) : "l"(a), "l"(b));
}
__device__ __forceinline__ void unpack2(ull p, float& lo, float& hi) {
    unsigned int a, b;
    asm("mov.b64 {%0, %1}, %2;" : "=r"(a), "=r"(b) : "l"(p));
    lo = __uint_as_float(a);
    hi = __uint_as_float(b);
}

// ---------------------------------------------------------------------------
// Pass 1: partial column sums of y = x[:, :, :D] over T chunks.
// ---------------------------------------------------------------------------
__global__ void mean_partial_kernel(const float* __restrict__ x) {
    const int b = blockIdx.x;
    const int c = blockIdx.y;
    const int d = threadIdx.x;
    const float* p = x + ((size_t)b * Tdim + (size_t)c * TCHUNK) * CH3 + d;
    float s0 = 0.f, s1 = 0.f, s2 = 0.f, s3 = 0.f;
#pragma unroll 4
    for (int t = 0; t < TCHUNK; t += 4) {
        s0 += p[(size_t)(t + 0) * CH3];
        s1 += p[(size_t)(t + 1) * CH3];
        s2 += p[(size_t)(t + 2) * CH3];
        s3 += p[(size_t)(t + 3) * CH3];
    }
    g_partial[(b * NCHUNK + c) * Ddim + d] = (s0 + s1) + (s2 + s3);
}

// ---------------------------------------------------------------------------
// Pass 2: fused exp / softmax / mean-subtract / matvec / outputs.
// Each warp handles 8 rows (4 row-pairs); f32x2 accumulators packed over the
// row-pair dimension so K values (reused across pairs) are duplicated once.
// ---------------------------------------------------------------------------
__global__ void __launch_bounds__(256, 2)
cci_main_kernel(const float* __restrict__ x,
                const float* __restrict__ kmat,
                float* __restrict__ out) {
    extern __shared__ float smem[];
    float* Ks = smem;                       // 128*128
    float* means = Ks + Ddim * Ddim;        // 128
    float* vbuf = means + Ddim;             // NWARPS * 4 pairs * 256 floats

    const int tid = threadIdx.x;
    const int w = tid >> 5;
    const int lane = tid & 31;

    // Stage kernel matrix (float4-coalesced).
    {
        const float4* src = (const float4*)kmat;
        float4* dst = (float4*)Ks;
#pragma unroll
        for (int i = tid; i < (Ddim * Ddim) / 4; i += 256) dst[i] = src[i];
    }

    const int row0 = blockIdx.x * ROWS_PER_BLOCK + w * ROWS_PER_WARP;
    const int b = (blockIdx.x * ROWS_PER_BLOCK) / Tdim;  // 64 | 1024 -> one b per block

    if (tid < Ddim) {
        float m = 0.f;
#pragma unroll
        for (int c = 0; c < NCHUNK; ++c) m += g_partial[(b * NCHUNK + c) * Ddim + tid];
        means[tid] = m * (1.0f / Tdim);
    }
    __syncthreads();

    const float4 mn = *(const float4*)(means + 4 * lane);
    float* pb = vbuf + w * 1024;   // 4 pairs * 256 floats

    // ---- prologue: exp / softmax / v, stored row-pair interleaved ----
#pragma unroll
    for (int p = 0; p < 4; ++p) {
        float4 vq[2];
#pragma unroll
        for (int q = 0; q < 2; ++q) {
            const int row = row0 + 2 * p + q;
            const float* xr = x + (size_t)row * CH3;
            const float4 y  = *(const float4*)(xr + 4 * lane);
            const float4 wv = *(const float4*)(xr + Ddim + 4 * lane);

            float4 inten;
            inten.x = __expf(wv.x);
            inten.y = __expf(wv.y);
            inten.z = __expf(wv.z);
            inten.w = __expf(wv.w);
            *(float4*)(out + (size_t)row * CH3 + Ddim + 4 * lane) = inten;

            float s = (inten.x + inten.y) + (inten.z + inten.w);
#pragma unroll
            for (int off = 16; off; off >>= 1)
                s += __shfl_xor_sync(0xffffffffu, s, off);
            const float rs = 1.0f / s;

            vq[q].x = inten.x * rs * (y.x - mn.x);
            vq[q].y = inten.y * rs * (y.y - mn.y);
            vq[q].z = inten.z * rs * (y.z - mn.z);
            vq[q].w = inten.w * rs * (y.w - mn.w);
        }
        // interleave: words j*2+q.  Lane owns j = 4*lane..4*lane+3.
        float4 c0, c1;
        c0.x = vq[0].x; c0.y = vq[1].x; c0.z = vq[0].y; c0.w = vq[1].y;
        c1.x = vq[0].z; c1.y = vq[1].z; c1.z = vq[0].w; c1.w = vq[1].w;
        *(float4*)(pb + p * 256 + 8 * lane)     = c0;
        *(float4*)(pb + p * 256 + 8 * lane + 4) = c1;
    }
    __syncwarp();

    // ---- matvec: out[c] = sum_j v[j] * K[j][c], 4 row-pairs at once ----
    ull acc[4][4];
#pragma unroll
    for (int p = 0; p < 4; ++p)
#pragma unroll
        for (int c = 0; c < 4; ++c) acc[p][c] = 0ull;

#pragma unroll 8
    for (int jg = 0; jg < 32; ++jg) {
        const int j = 4 * jg;
        float4 kk[4];
#pragma unroll
        for (int u = 0; u < 4; ++u)
            kk[u] = *(const float4*)(Ks + (j + u) * Ddim + 4 * lane);

        ull kd[4][4];
#pragma unroll
        for (int u = 0; u < 4; ++u) {
            kd[u][0] = dup2(kk[u].x);
            kd[u][1] = dup2(kk[u].y);
            kd[u][2] = dup2(kk[u].z);
            kd[u][3] = dup2(kk[u].w);
        }

#pragma unroll
        for (int p = 0; p < 4; ++p) {
            // {v_even[j], v_odd[j]}, {v_even[j+1], v_odd[j+1]}, ... broadcast
            const ulonglong2 va = *(const ulonglong2*)(pb + p * 256 + 8 * jg);
            const ulonglong2 vb = *(const ulonglong2*)(pb + p * 256 + 8 * jg + 4);
            ull vp[4];
            vp[0] = va.x; vp[1] = va.y; vp[2] = vb.x; vp[3] = vb.y;
#pragma unroll
            for (int u = 0; u < 4; ++u) {
                fma2(acc[p][0], vp[u], kd[u][0]);
                fma2(acc[p][1], vp[u], kd[u][1]);
                fma2(acc[p][2], vp[u], kd[u][2]);
                fma2(acc[p][3], vp[u], kd[u][3]);
            }
        }
    }

    // ---- epilogue: smooth = acc + mean; y_trans = y_obs - smooth ----
#pragma unroll
    for (int p = 0; p < 4; ++p) {
        float lo[4], hi[4];
#pragma unroll
        for (int c = 0; c < 4; ++c) unpack2(acc[p][c], lo[c], hi[c]);

#pragma unroll
        for (int q = 0; q < 2; ++q) {
            const int row = row0 + 2 * p + q;
            float* outr = out + (size_t)row * CH3;
            const float* sv = q ? hi : lo;

            float4 sm4;
            sm4.x = sv[0] + mn.x;
            sm4.y = sv[1] + mn.y;
            sm4.z = sv[2] + mn.z;
            sm4.w = sv[3] + mn.w;
            *(float4*)(outr + 4 * lane) = sm4;

            const float4 yo = *(const float4*)(x + (size_t)row * CH3 + 2 * Ddim + 4 * lane);
            float4 yt;
            yt.x = yo.x - sm4.x;
            yt.y = yo.y - sm4.y;
            yt.z = yo.z - sm4.z;
            yt.w = yo.w - sm4.w;
            *(float4*)(outr + 2 * Ddim + 4 * lane) = yt;
        }
    }
}

// ---------------------------------------------------------------------------
extern "C" void kernel_launch(void* const* d_in, const int* in_sizes, int n_in,
                              void* d_out, int out_size) {
    const float* x;
    const float* kmat;
    if (in_sizes[0] == Ddim * Ddim) {
        kmat = (const float*)d_in[0];
        x = (const float*)d_in[1];
    } else {
        x = (const float*)d_in[0];
        kmat = (const float*)d_in[1];
    }
    float* out = (float*)d_out;

    const int smem_bytes =
        (Ddim * Ddim + Ddim + NWARPS * 4 * 256) * sizeof(float);
    cudaFuncSetAttribute(cci_main_kernel,
                         cudaFuncAttributeMaxDynamicSharedMemorySize, smem_bytes);

    mean_partial_kernel<<<dim3(Bdim, NCHUNK), Ddim>>>(x);
    cci_main_kernel<<<(Bdim * Tdim) / ROWS_PER_BLOCK, 256, smem_bytes>>>(x, kmat, out);
}

// round 5
// speedup vs baseline: 1.9850x; 1.0129x over previous
#include <cuda_runtime.h>
#include <cuda_bf16.h>
#include <cstdint>

#define Ddim 128
#define Tdim 1024
#define Bdim 128
#define CH3 (3 * Ddim)
#define NCHUNK 8
#define TCHUNK (Tdim / NCHUNK)
#define ROWS_PB 256
#define NWARPS 16

// ---------------------------------------------------------------------------
// Device globals (no runtime allocation allowed)
// ---------------------------------------------------------------------------
__device__ float g_partial[Bdim * NCHUNK * Ddim];
// Pre-packed B fragments: [n(16)][k(8)][lane(32)] -> {b0_hi, b1_hi, b0_lo, b1_lo}
__device__ uint4 g_Bpk[16 * 8 * 32];

// SMEM byte offsets (dynamic smem, 16B-aligned by default)
#define SM_B     0                                  // 65536 B
#define SM_A_HI  65536
#define A_STRIDE 272                                // 136 bf16, conflict-free ldmatrix
#define WARP_A   (16 * A_STRIDE)                    // 4352 B per warp
#define SM_A_LO  (SM_A_HI + NWARPS * WARP_A)        // 135168
#define SM_MEANS (SM_A_LO + NWARPS * WARP_A)        // 204800
#define SM_TOTAL (SM_MEANS + 512)                   // 205312

// ---------------------------------------------------------------------------
__device__ __forceinline__ uint32_t smem_u32(const void* p) {
    uint32_t a;
    asm("{ .reg .u64 t; cvta.to.shared.u64 t, %1; cvt.u32.u64 %0, t; }" : "=r"(a) : "l"(p));
    return a;
}

__device__ __forceinline__ void mma16816(float* d, const uint32_t* a,
                                         uint32_t b0, uint32_t b1) {
    asm volatile(
        "mma.sync.aligned.m16n8k16.row.col.f32.bf16.bf16.f32 "
        "{%0,%1,%2,%3}, {%4,%5,%6,%7}, {%8,%9}, {%0,%1,%2,%3};"
        : "+f"(d[0]), "+f"(d[1]), "+f"(d[2]), "+f"(d[3])
        : "r"(a[0]), "r"(a[1]), "r"(a[2]), "r"(a[3]), "r"(b0), "r"(b1));
}

__device__ __forceinline__ void ldmatrix4(uint32_t* r, uint32_t addr) {
    asm volatile("ldmatrix.sync.aligned.m8n8.x4.shared.b16 {%0,%1,%2,%3}, [%4];"
                 : "=r"(r[0]), "=r"(r[1]), "=r"(r[2]), "=r"(r[3]) : "r"(addr));
}

// ---------------------------------------------------------------------------
// Pass 1: mean partials; blocks with y==NCHUNK build the packed B fragments.
// ---------------------------------------------------------------------------
__global__ void prep_kernel(const float* __restrict__ x, const float* __restrict__ kmat) {
    if (blockIdx.y == NCHUNK) {
        const int e = blockIdx.x * blockDim.x + threadIdx.x;
        if (e < 16 * 8 * 32) {
            const int n = e >> 8, k = (e >> 5) & 7, lane = e & 31;
            const int g = lane >> 2, tig = lane & 3;
            const int col = n * 8 + g;
            const int r0 = k * 16 + tig * 2;
            const float f00 = kmat[(r0 + 0) * Ddim + col];
            const float f01 = kmat[(r0 + 1) * Ddim + col];
            const float f10 = kmat[(r0 + 8) * Ddim + col];
            const float f11 = kmat[(r0 + 9) * Ddim + col];
            __nv_bfloat162 b0h = __floats2bfloat162_rn(f00, f01);
            __nv_bfloat162 b1h = __floats2bfloat162_rn(f10, f11);
            __nv_bfloat162 b0l = __floats2bfloat162_rn(f00 - __bfloat162float(b0h.x),
                                                       f01 - __bfloat162float(b0h.y));
            __nv_bfloat162 b1l = __floats2bfloat162_rn(f10 - __bfloat162float(b1h.x),
                                                       f11 - __bfloat162float(b1h.y));
            uint4 v;
            v.x = *(uint32_t*)&b0h; v.y = *(uint32_t*)&b1h;
            v.z = *(uint32_t*)&b0l; v.w = *(uint32_t*)&b1l;
            g_Bpk[e] = v;
        }
        return;
    }
    const int b = blockIdx.x;
    const int c = blockIdx.y;
    const int d = threadIdx.x;
    const float* p = x + ((size_t)b * Tdim + (size_t)c * TCHUNK) * CH3 + d;
    float s0 = 0.f, s1 = 0.f, s2 = 0.f, s3 = 0.f;
#pragma unroll 4
    for (int t = 0; t < TCHUNK; t += 4) {
        s0 += p[(size_t)(t + 0) * CH3];
        s1 += p[(size_t)(t + 1) * CH3];
        s2 += p[(size_t)(t + 2) * CH3];
        s3 += p[(size_t)(t + 3) * CH3];
    }
    g_partial[(b * NCHUNK + c) * Ddim + d] = (s0 + s1) + (s2 + s3);
}

// ---------------------------------------------------------------------------
// Pass 2: fused exp/softmax/v + bf16-split HMMA GEMM + direct epilogue.
// Block: 512 threads = 16 warps, 256 rows. Grid: 512.
// ---------------------------------------------------------------------------
__global__ void __launch_bounds__(512, 1)
cci_main(const float* __restrict__ x, float* __restrict__ out) {
    extern __shared__ char sm[];
    const uint32_t sbase = smem_u32(sm);

    const int tid = threadIdx.x;
    const int w = tid >> 5;
    const int lane = tid & 31;
    const int g = lane >> 2;      // group id (row within fragment)
    const int tig = lane & 3;     // thread in group
    const int row0 = blockIdx.x * ROWS_PB;
    const int b = row0 / Tdim;

    // Stage packed B fragments (raw 64KB copy).
    {
        const uint4* src = g_Bpk;
        uint4* dst = (uint4*)(sm + SM_B);
#pragma unroll
        for (int i = tid; i < 4096; i += 512) dst[i] = src[i];
    }

    // Finalize mean for this b.
    if (tid < Ddim) {
        float m = 0.f;
#pragma unroll
        for (int c = 0; c < NCHUNK; ++c) m += g_partial[(b * NCHUNK + c) * Ddim + tid];
        ((float*)(sm + SM_MEANS))[tid] = m * (1.0f / Tdim);
    }
    __syncthreads();

    const float4 mn = *(const float4*)(sm + SM_MEANS + 16 * lane);

    // ---- prologue: 16 rows/warp; A = hi/lo bf16 of softmax(w)*(y-mean) ----
    char* aHi = sm + SM_A_HI + w * WARP_A;
    char* aLo = sm + SM_A_LO + w * WARP_A;
#pragma unroll 2
    for (int i = 0; i < 16; ++i) {
        const int row = row0 + w * 16 + i;
        const float* xr = x + (size_t)row * CH3;

        const float4 y  = *(const float4*)(xr + 4 * lane);
        const float4 wv = *(const float4*)(xr + Ddim + 4 * lane);

        float4 inten;
        inten.x = __expf(wv.x);
        inten.y = __expf(wv.y);
        inten.z = __expf(wv.z);
        inten.w = __expf(wv.w);
        *(float4*)(out + (size_t)row * CH3 + Ddim + 4 * lane) = inten;

        float s = (inten.x + inten.y) + (inten.z + inten.w);
#pragma unroll
        for (int off = 16; off; off >>= 1) s += __shfl_xor_sync(0xffffffffu, s, off);
        const float rs = 1.0f / s;

        float4 v;
        v.x = inten.x * rs * (y.x - mn.x);
        v.y = inten.y * rs * (y.y - mn.y);
        v.z = inten.z * rs * (y.z - mn.z);
        v.w = inten.w * rs * (y.w - mn.w);

        __nv_bfloat162 h01 = __floats2bfloat162_rn(v.x, v.y);
        __nv_bfloat162 h23 = __floats2bfloat162_rn(v.z, v.w);
        __nv_bfloat162 l01 = __floats2bfloat162_rn(v.x - __bfloat162float(h01.x),
                                                   v.y - __bfloat162float(h01.y));
        __nv_bfloat162 l23 = __floats2bfloat162_rn(v.z - __bfloat162float(h23.x),
                                                   v.w - __bfloat162float(h23.y));
        uint2 ph, pl;
        ph.x = *(uint32_t*)&h01; ph.y = *(uint32_t*)&h23;
        pl.x = *(uint32_t*)&l01; pl.y = *(uint32_t*)&l23;
        *(uint2*)(aHi + i * A_STRIDE + 8 * lane) = ph;
        *(uint2*)(aLo + i * A_STRIDE + 8 * lane) = pl;
    }
    __syncthreads();

    // ---- GEMM: acc = A_hi@B_hi + A_hi@B_lo + A_lo@B_hi (fp32 accum) ----
    float acc[16][4];
#pragma unroll
    for (int n = 0; n < 16; ++n)
#pragma unroll
        for (int c = 0; c < 4; ++c) acc[n][c] = 0.f;

    // ldmatrix address: row = lane%16, 16B-column-block = lane/16
    const uint32_t aHiAddr = sbase + SM_A_HI + w * WARP_A + (lane & 15) * A_STRIDE + (lane >> 4) * 16;
    const uint32_t aLoAddr = aHiAddr + (SM_A_LO - SM_A_HI);
    const uint32_t bBase = sbase + SM_B + lane * 16;

#pragma unroll
    for (int k = 0; k < 8; ++k) {
        uint32_t ah[4], al[4];
        ldmatrix4(ah, aHiAddr + k * 32);
        ldmatrix4(al, aLoAddr + k * 32);
#pragma unroll
        for (int n = 0; n < 16; ++n) {
            uint4 bf;
            asm volatile("ld.shared.v4.b32 {%0,%1,%2,%3}, [%4];"
                         : "=r"(bf.x), "=r"(bf.y), "=r"(bf.z), "=r"(bf.w)
                         : "r"(bBase + (uint32_t)((n * 8 + k) * 512)));
            mma16816(acc[n], ah, bf.x, bf.y);   // hi * hi
            mma16816(acc[n], ah, bf.z, bf.w);   // hi * lo
            mma16816(acc[n], al, bf.x, bf.y);   // lo * hi
        }
    }

    // ---- epilogue: smooth = acc + mean; y_trans = y_obs - smooth ----
    const int ra = row0 + w * 16 + g;
    const int rb = ra + 8;
    const float* meansp = (const float*)(sm + SM_MEANS);
#pragma unroll
    for (int n = 0; n < 16; ++n) {
        const int col = n * 8 + tig * 2;
        const float2 m2 = *(const float2*)(meansp + col);

        float2 sa, sb;
        sa.x = acc[n][0] + m2.x;
        sa.y = acc[n][1] + m2.y;
        sb.x = acc[n][2] + m2.x;
        sb.y = acc[n][3] + m2.y;
        *(float2*)(out + (size_t)ra * CH3 + col) = sa;
        *(float2*)(out + (size_t)rb * CH3 + col) = sb;

        const float2 ya = *(const float2*)(x + (size_t)ra * CH3 + 2 * Ddim + col);
        const float2 yb = *(const float2*)(x + (size_t)rb * CH3 + 2 * Ddim + col);
        float2 ta, tb;
        ta.x = ya.x - sa.x;
        ta.y = ya.y - sa.y;
        tb.x = yb.x - sb.x;
        tb.y = yb.y - sb.y;
        *(float2*)(out + (size_t)ra * CH3 + 2 * Ddim + col) = ta;
        *(float2*)(out + (size_t)rb * CH3 + 2 * Ddim + col) = tb;
    }
}

// ---------------------------------------------------------------------------
extern "C" void kernel_launch(void* const* d_in, const int* in_sizes, int n_in,
                              void* d_out, int out_size) {
    const float* x;
    const float* kmat;
    if (in_sizes[0] == Ddim * Ddim) {
        kmat = (const float*)d_in[0];
        x = (const float*)d_in[1];
    } else {
        x = (const float*)d_in[0];
        kmat = (const float*)d_in[1];
    }
    float* out = (float*)d_out;

    cudaFuncSetAttribute(cci_main, cudaFuncAttributeMaxDynamicSharedMemorySize, SM_TOTAL);

    prep_kernel<<<dim3(Bdim, NCHUNK + 1), Ddim>>>(x, kmat);
    cci_main<<<(Bdim * Tdim) / ROWS_PB, 512, SM_TOTAL>>>(x, out);
}

// round 6
// speedup vs baseline: 2.2453x; 1.1312x over previous
#include <cuda_runtime.h>
#include <cuda_bf16.h>
#include <cstdint>

#define Ddim 128
#define Tdim 1024
#define Bdim 128
#define CH3 (3 * Ddim)
#define NCHUNK 8
#define TCHUNK (Tdim / NCHUNK)
#define ROWS_PB 256
#define NWARPS 16

// ---------------------------------------------------------------------------
// Device globals (no runtime allocation allowed)
// ---------------------------------------------------------------------------
__device__ float g_partial[Bdim * NCHUNK * Ddim];
// Pre-packed B fragments: [n(16)][k(8)][lane(32)] -> {b0_hi, b1_hi, b0_lo, b1_lo}
__device__ uint4 g_Bpk[16 * 8 * 32];

// SMEM byte offsets
#define SM_B     0                                  // 65536 B
#define SM_A_HI  65536
#define A_STRIDE 272                                // conflict-free ldmatrix
#define WARP_A   (16 * A_STRIDE)
#define SM_A_LO  (SM_A_HI + NWARPS * WARP_A)
#define SM_MEANS (SM_A_LO + NWARPS * WARP_A)
#define SM_TOTAL (SM_MEANS + 512)

// ---------------------------------------------------------------------------
__device__ __forceinline__ uint32_t smem_u32(const void* p) {
    uint32_t a;
    asm("{ .reg .u64 t; cvta.to.shared.u64 t, %1; cvt.u32.u64 %0, t; }" : "=r"(a) : "l"(p));
    return a;
}

__device__ __forceinline__ void mma16816(float* d, const uint32_t* a,
                                         uint32_t b0, uint32_t b1) {
    asm volatile(
        "mma.sync.aligned.m16n8k16.row.col.f32.bf16.bf16.f32 "
        "{%0,%1,%2,%3}, {%4,%5,%6,%7}, {%8,%9}, {%0,%1,%2,%3};"
        : "+f"(d[0]), "+f"(d[1]), "+f"(d[2]), "+f"(d[3])
        : "r"(a[0]), "r"(a[1]), "r"(a[2]), "r"(a[3]), "r"(b0), "r"(b1));
}

__device__ __forceinline__ void ldmatrix4(uint32_t* r, uint32_t addr) {
    asm volatile("ldmatrix.sync.aligned.m8n8.x4.shared.b16 {%0,%1,%2,%3}, [%4];"
                 : "=r"(r[0]), "=r"(r[1]), "=r"(r[2]), "=r"(r[3]) : "r"(addr));
}

// ---------------------------------------------------------------------------
// Pass 1: mean partials; blocks with y==NCHUNK build the packed B fragments.
// ---------------------------------------------------------------------------
__global__ void prep_kernel(const float* __restrict__ x, const float* __restrict__ kmat) {
    if (blockIdx.y == NCHUNK) {
        const int e = blockIdx.x * blockDim.x + threadIdx.x;
        if (e < 16 * 8 * 32) {
            const int n = e >> 8, k = (e >> 5) & 7, lane = e & 31;
            const int g = lane >> 2, tig = lane & 3;
            const int col = n * 8 + g;
            const int r0 = k * 16 + tig * 2;
            const float f00 = kmat[(r0 + 0) * Ddim + col];
            const float f01 = kmat[(r0 + 1) * Ddim + col];
            const float f10 = kmat[(r0 + 8) * Ddim + col];
            const float f11 = kmat[(r0 + 9) * Ddim + col];
            __nv_bfloat162 b0h = __floats2bfloat162_rn(f00, f01);
            __nv_bfloat162 b1h = __floats2bfloat162_rn(f10, f11);
            __nv_bfloat162 b0l = __floats2bfloat162_rn(f00 - __bfloat162float(b0h.x),
                                                       f01 - __bfloat162float(b0h.y));
            __nv_bfloat162 b1l = __floats2bfloat162_rn(f10 - __bfloat162float(b1h.x),
                                                       f11 - __bfloat162float(b1h.y));
            uint4 v;
            v.x = *(uint32_t*)&b0h; v.y = *(uint32_t*)&b1h;
            v.z = *(uint32_t*)&b0l; v.w = *(uint32_t*)&b1l;
            g_Bpk[e] = v;
        }
        return;
    }
    const int b = blockIdx.x;
    const int c = blockIdx.y;
    const int d = threadIdx.x;
    const float* p = x + ((size_t)b * Tdim + (size_t)c * TCHUNK) * CH3 + d;
    float s0 = 0.f, s1 = 0.f, s2 = 0.f, s3 = 0.f;
#pragma unroll 4
    for (int t = 0; t < TCHUNK; t += 4) {
        s0 += p[(size_t)(t + 0) * CH3];
        s1 += p[(size_t)(t + 1) * CH3];
        s2 += p[(size_t)(t + 2) * CH3];
        s3 += p[(size_t)(t + 3) * CH3];
    }
    g_partial[(b * NCHUNK + c) * Ddim + d] = (s0 + s1) + (s2 + s3);
}

// ---------------------------------------------------------------------------
// Pass 2: per-warp independent pipeline (prologue -> HMMA GEMM -> epilogue).
// Only ONE block-wide sync (after shared B + means staging); after that each
// warp owns its private 16-row A tile, so warps drift and overlap memory
// phases with tensor phases naturally.
// ---------------------------------------------------------------------------
__global__ void __launch_bounds__(512, 1)
cci_main(const float* __restrict__ x, float* __restrict__ out) {
    extern __shared__ char sm[];
    const uint32_t sbase = smem_u32(sm);

    const int tid = threadIdx.x;
    const int w = tid >> 5;
    const int lane = tid & 31;
    const int g = lane >> 2;
    const int tig = lane & 3;
    const int row0 = blockIdx.x * ROWS_PB;
    const int b = row0 / Tdim;

    // Stage packed B fragments (raw 64KB copy).
    {
        const uint4* src = g_Bpk;
        uint4* dst = (uint4*)(sm + SM_B);
#pragma unroll
        for (int i = tid; i < 4096; i += 512) dst[i] = src[i];
    }

    // Finalize mean for this b.
    if (tid < Ddim) {
        float m = 0.f;
#pragma unroll
        for (int c = 0; c < NCHUNK; ++c) m += g_partial[(b * NCHUNK + c) * Ddim + tid];
        ((float*)(sm + SM_MEANS))[tid] = m * (1.0f / Tdim);
    }
    __syncthreads();   // the ONLY block-wide sync

    const float4 mn = *(const float4*)(sm + SM_MEANS + 16 * lane);

    // ---- prologue: 16 rows/warp in batches of 4 (8 LDG.128 in flight) ----
    char* aHi = sm + SM_A_HI + w * WARP_A;
    char* aLo = sm + SM_A_LO + w * WARP_A;
#pragma unroll
    for (int i0 = 0; i0 < 16; i0 += 4) {
        float4 y[4], wv[4];
#pragma unroll
        for (int q = 0; q < 4; ++q) {
            const float* xr = x + (size_t)(row0 + w * 16 + i0 + q) * CH3;
            y[q]  = *(const float4*)(xr + 4 * lane);
            wv[q] = *(const float4*)(xr + Ddim + 4 * lane);
        }
#pragma unroll
        for (int q = 0; q < 4; ++q) {
            const int i = i0 + q;
            const int row = row0 + w * 16 + i;

            float4 inten;
            inten.x = __expf(wv[q].x);
            inten.y = __expf(wv[q].y);
            inten.z = __expf(wv[q].z);
            inten.w = __expf(wv[q].w);
            *(float4*)(out + (size_t)row * CH3 + Ddim + 4 * lane) = inten;

            float s = (inten.x + inten.y) + (inten.z + inten.w);
#pragma unroll
            for (int off = 16; off; off >>= 1) s += __shfl_xor_sync(0xffffffffu, s, off);
            const float rs = 1.0f / s;

            float4 v;
            v.x = inten.x * rs * (y[q].x - mn.x);
            v.y = inten.y * rs * (y[q].y - mn.y);
            v.z = inten.z * rs * (y[q].z - mn.z);
            v.w = inten.w * rs * (y[q].w - mn.w);

            __nv_bfloat162 h01 = __floats2bfloat162_rn(v.x, v.y);
            __nv_bfloat162 h23 = __floats2bfloat162_rn(v.z, v.w);
            __nv_bfloat162 l01 = __floats2bfloat162_rn(v.x - __bfloat162float(h01.x),
                                                       v.y - __bfloat162float(h01.y));
            __nv_bfloat162 l23 = __floats2bfloat162_rn(v.z - __bfloat162float(h23.x),
                                                       v.w - __bfloat162float(h23.y));
            uint2 ph, pl;
            ph.x = *(uint32_t*)&h01; ph.y = *(uint32_t*)&h23;
            pl.x = *(uint32_t*)&l01; pl.y = *(uint32_t*)&l23;
            *(uint2*)(aHi + i * A_STRIDE + 8 * lane) = ph;
            *(uint2*)(aLo + i * A_STRIDE + 8 * lane) = pl;
        }
    }
    __syncwarp();   // warp-private A tile ready for ldmatrix

    // ---- GEMM: acc = A_hi@B_hi + A_hi@B_lo + A_lo@B_hi (fp32 accum) ----
    float acc[16][4];
#pragma unroll
    for (int n = 0; n < 16; ++n)
#pragma unroll
        for (int c = 0; c < 4; ++c) acc[n][c] = 0.f;

    const uint32_t aHiAddr = sbase + SM_A_HI + w * WARP_A + (lane & 15) * A_STRIDE + (lane >> 4) * 16;
    const uint32_t aLoAddr = aHiAddr + (SM_A_LO - SM_A_HI);
    const uint32_t bBase = sbase + SM_B + lane * 16;

#pragma unroll
    for (int k = 0; k < 8; ++k) {
        uint32_t ah[4], al[4];
        ldmatrix4(ah, aHiAddr + k * 32);
        ldmatrix4(al, aLoAddr + k * 32);
#pragma unroll
        for (int n = 0; n < 16; ++n) {
            uint4 bf;
            asm volatile("ld.shared.v4.b32 {%0,%1,%2,%3}, [%4];"
                         : "=r"(bf.x), "=r"(bf.y), "=r"(bf.z), "=r"(bf.w)
                         : "r"(bBase + (uint32_t)((n * 8 + k) * 512)));
            mma16816(acc[n], ah, bf.x, bf.y);   // hi * hi
            mma16816(acc[n], ah, bf.z, bf.w);   // hi * lo
            mma16816(acc[n], al, bf.x, bf.y);   // lo * hi
        }
    }

    // ---- epilogue: smooth = acc + mean; y_trans = y_obs - smooth ----
    const int ra = row0 + w * 16 + g;
    const int rb = ra + 8;
    const float* meansp = (const float*)(sm + SM_MEANS);
#pragma unroll
    for (int n = 0; n < 16; ++n) {
        const int col = n * 8 + tig * 2;
        const float2 m2 = *(const float2*)(meansp + col);

        float2 sa, sb;
        sa.x = acc[n][0] + m2.x;
        sa.y = acc[n][1] + m2.y;
        sb.x = acc[n][2] + m2.x;
        sb.y = acc[n][3] + m2.y;
        *(float2*)(out + (size_t)ra * CH3 + col) = sa;
        *(float2*)(out + (size_t)rb * CH3 + col) = sb;

        const float2 ya = *(const float2*)(x + (size_t)ra * CH3 + 2 * Ddim + col);
        const float2 yb = *(const float2*)(x + (size_t)rb * CH3 + 2 * Ddim + col);
        float2 ta, tb;
        ta.x = ya.x - sa.x;
        ta.y = ya.y - sa.y;
        tb.x = yb.x - sb.x;
        tb.y = yb.y - sb.y;
        *(float2*)(out + (size_t)ra * CH3 + 2 * Ddim + col) = ta;
        *(float2*)(out + (size_t)rb * CH3 + 2 * Ddim + col) = tb;
    }
}

// ---------------------------------------------------------------------------
extern "C" void kernel_launch(void* const* d_in, const int* in_sizes, int n_in,
                              void* d_out, int out_size) {
    const float* x;
    const float* kmat;
    if (in_sizes[0] == Ddim * Ddim) {
        kmat = (const float*)d_in[0];
        x = (const float*)d_in[1];
    } else {
        x = (const float*)d_in[0];
        kmat = (const float*)d_in[1];
    }
    float* out = (float*)d_out;

    cudaFuncSetAttribute(cci_main, cudaFuncAttributeMaxDynamicSharedMemorySize, SM_TOTAL);

    prep_kernel<<<dim3(Bdim, NCHUNK + 1), Ddim>>>(x, kmat);
    cci_main<<<(Bdim * Tdim) / ROWS_PB, 512, SM_TOTAL>>>(x, out);
}

// round 7
// speedup vs baseline: 2.2491x; 1.0017x over previous
#include <cuda_runtime.h>
#include <cuda_bf16.h>
#include <cstdint>

#define Ddim 128
#define Tdim 1024
#define Bdim 128
#define CH3 (3 * Ddim)
#define NCHUNK 8
#define TCHUNK (Tdim / NCHUNK)
#define ROWS_PB 256
#define NWARPS 16

// ---------------------------------------------------------------------------
// Device globals (no runtime allocation allowed)
// ---------------------------------------------------------------------------
__device__ float g_partial[Bdim * NCHUNK * Ddim];
// Pre-packed B fragments: [n(16)][k(8)][lane(32)] -> {b0_hi, b1_hi, b0_lo, b1_lo}
__device__ uint4 g_Bpk[16 * 8 * 32];

// SMEM byte offsets
#define SM_B     0                                  // 65536 B
#define SM_A_HI  65536
#define A_STRIDE 272                                // conflict-free ldmatrix
#define WARP_A   (16 * A_STRIDE)
#define SM_A_LO  (SM_A_HI + NWARPS * WARP_A)
#define SM_MEANS (SM_A_LO + NWARPS * WARP_A)
#define SM_TOTAL (SM_MEANS + 512)

// ---------------------------------------------------------------------------
__device__ __forceinline__ uint32_t smem_u32(const void* p) {
    uint32_t a;
    asm("{ .reg .u64 t; cvta.to.shared.u64 t, %1; cvt.u32.u64 %0, t; }" : "=r"(a) : "l"(p));
    return a;
}

__device__ __forceinline__ void mma16816(float* d, const uint32_t* a,
                                         uint32_t b0, uint32_t b1) {
    asm volatile(
        "mma.sync.aligned.m16n8k16.row.col.f32.bf16.bf16.f32 "
        "{%0,%1,%2,%3}, {%4,%5,%6,%7}, {%8,%9}, {%0,%1,%2,%3};"
        : "+f"(d[0]), "+f"(d[1]), "+f"(d[2]), "+f"(d[3])
        : "r"(a[0]), "r"(a[1]), "r"(a[2]), "r"(a[3]), "r"(b0), "r"(b1));
}

__device__ __forceinline__ void ldmatrix4(uint32_t* r, uint32_t addr) {
    asm volatile("ldmatrix.sync.aligned.m8n8.x4.shared.b16 {%0,%1,%2,%3}, [%4];"
                 : "=r"(r[0]), "=r"(r[1]), "=r"(r[2]), "=r"(r[3]) : "r"(addr));
}

// ---------------------------------------------------------------------------
// Pass 1: mean partials; blocks with y==NCHUNK build the packed B fragments.
// ---------------------------------------------------------------------------
__global__ void prep_kernel(const float* __restrict__ x, const float* __restrict__ kmat) {
    if (blockIdx.y == NCHUNK) {
        const int e = blockIdx.x * blockDim.x + threadIdx.x;
        if (e < 16 * 8 * 32) {
            const int n = e >> 8, k = (e >> 5) & 7, lane = e & 31;
            const int g = lane >> 2, tig = lane & 3;
            const int col = n * 8 + g;
            const int r0 = k * 16 + tig * 2;
            const float f00 = kmat[(r0 + 0) * Ddim + col];
            const float f01 = kmat[(r0 + 1) * Ddim + col];
            const float f10 = kmat[(r0 + 8) * Ddim + col];
            const float f11 = kmat[(r0 + 9) * Ddim + col];
            __nv_bfloat162 b0h = __floats2bfloat162_rn(f00, f01);
            __nv_bfloat162 b1h = __floats2bfloat162_rn(f10, f11);
            __nv_bfloat162 b0l = __floats2bfloat162_rn(f00 - __bfloat162float(b0h.x),
                                                       f01 - __bfloat162float(b0h.y));
            __nv_bfloat162 b1l = __floats2bfloat162_rn(f10 - __bfloat162float(b1h.x),
                                                       f11 - __bfloat162float(b1h.y));
            uint4 v;
            v.x = *(uint32_t*)&b0h; v.y = *(uint32_t*)&b1h;
            v.z = *(uint32_t*)&b0l; v.w = *(uint32_t*)&b1l;
            g_Bpk[e] = v;
        }
        return;
    }
    const int b = blockIdx.x;
    const int c = blockIdx.y;
    const int d = threadIdx.x;
    const float* p = x + ((size_t)b * Tdim + (size_t)c * TCHUNK) * CH3 + d;
    float s0 = 0.f, s1 = 0.f, s2 = 0.f, s3 = 0.f;
#pragma unroll 4
    for (int t = 0; t < TCHUNK; t += 4) {
        s0 += p[(size_t)(t + 0) * CH3];
        s1 += p[(size_t)(t + 1) * CH3];
        s2 += p[(size_t)(t + 2) * CH3];
        s3 += p[(size_t)(t + 3) * CH3];
    }
    g_partial[(b * NCHUNK + c) * Ddim + d] = (s0 + s1) + (s2 + s3);
}

// ---------------------------------------------------------------------------
// Pass 2: per-warp independent pipeline (prologue -> HMMA GEMM -> epilogue).
// Only ONE block-wide sync (after shared B + means staging); after that each
// warp owns its private 16-row A tile, so warps drift and overlap memory
// phases with tensor phases naturally.
// ---------------------------------------------------------------------------
__global__ void __launch_bounds__(512, 1)
cci_main(const float* __restrict__ x, float* __restrict__ out) {
    extern __shared__ char sm[];
    const uint32_t sbase = smem_u32(sm);

    const int tid = threadIdx.x;
    const int w = tid >> 5;
    const int lane = tid & 31;
    const int g = lane >> 2;
    const int tig = lane & 3;
    const int row0 = blockIdx.x * ROWS_PB;
    const int b = row0 / Tdim;

    // Stage packed B fragments (raw 64KB copy).
    {
        const uint4* src = g_Bpk;
        uint4* dst = (uint4*)(sm + SM_B);
#pragma unroll
        for (int i = tid; i < 4096; i += 512) dst[i] = src[i];
    }

    // Finalize mean for this b.
    if (tid < Ddim) {
        float m = 0.f;
#pragma unroll
        for (int c = 0; c < NCHUNK; ++c) m += g_partial[(b * NCHUNK + c) * Ddim + tid];
        ((float*)(sm + SM_MEANS))[tid] = m * (1.0f / Tdim);
    }
    __syncthreads();   // the ONLY block-wide sync

    const float4 mn = *(const float4*)(sm + SM_MEANS + 16 * lane);

    // ---- prologue: 16 rows/warp in batches of 4 (8 LDG.128 in flight) ----
    char* aHi = sm + SM_A_HI + w * WARP_A;
    char* aLo = sm + SM_A_LO + w * WARP_A;
#pragma unroll
    for (int i0 = 0; i0 < 16; i0 += 4) {
        float4 y[4], wv[4];
#pragma unroll
        for (int q = 0; q < 4; ++q) {
            const float* xr = x + (size_t)(row0 + w * 16 + i0 + q) * CH3;
            y[q]  = *(const float4*)(xr + 4 * lane);
            wv[q] = *(const float4*)(xr + Ddim + 4 * lane);
        }
#pragma unroll
        for (int q = 0; q < 4; ++q) {
            const int i = i0 + q;
            const int row = row0 + w * 16 + i;

            float4 inten;
            inten.x = __expf(wv[q].x);
            inten.y = __expf(wv[q].y);
            inten.z = __expf(wv[q].z);
            inten.w = __expf(wv[q].w);
            *(float4*)(out + (size_t)row * CH3 + Ddim + 4 * lane) = inten;

            float s = (inten.x + inten.y) + (inten.z + inten.w);
#pragma unroll
            for (int off = 16; off; off >>= 1) s += __shfl_xor_sync(0xffffffffu, s, off);
            const float rs = 1.0f / s;

            float4 v;
            v.x = inten.x * rs * (y[q].x - mn.x);
            v.y = inten.y * rs * (y[q].y - mn.y);
            v.z = inten.z * rs * (y[q].z - mn.z);
            v.w = inten.w * rs * (y[q].w - mn.w);

            __nv_bfloat162 h01 = __floats2bfloat162_rn(v.x, v.y);
            __nv_bfloat162 h23 = __floats2bfloat162_rn(v.z, v.w);
            __nv_bfloat162 l01 = __floats2bfloat162_rn(v.x - __bfloat162float(h01.x),
                                                       v.y - __bfloat162float(h01.y));
            __nv_bfloat162 l23 = __floats2bfloat162_rn(v.z - __bfloat162float(h23.x),
                                                       v.w - __bfloat162float(h23.y));
            uint2 ph, pl;
            ph.x = *(uint32_t*)&h01; ph.y = *(uint32_t*)&h23;
            pl.x = *(uint32_t*)&l01; pl.y = *(uint32_t*)&l23;
            *(uint2*)(aHi + i * A_STRIDE + 8 * lane) = ph;
            *(uint2*)(aLo + i * A_STRIDE + 8 * lane) = pl;
        }
    }
    __syncwarp();   // warp-private A tile ready for ldmatrix

    // ---- GEMM: acc = A_hi@B_hi + A_hi@B_lo + A_lo@B_hi (fp32 accum) ----
    float acc[16][4];
#pragma unroll
    for (int n = 0; n < 16; ++n)
#pragma unroll
        for (int c = 0; c < 4; ++c) acc[n][c] = 0.f;

    const uint32_t aHiAddr = sbase + SM_A_HI + w * WARP_A + (lane & 15) * A_STRIDE + (lane >> 4) * 16;
    const uint32_t aLoAddr = aHiAddr + (SM_A_LO - SM_A_HI);
    const uint32_t bBase = sbase + SM_B + lane * 16;

#pragma unroll
    for (int k = 0; k < 8; ++k) {
        uint32_t ah[4], al[4];
        ldmatrix4(ah, aHiAddr + k * 32);
        ldmatrix4(al, aLoAddr + k * 32);
#pragma unroll
        for (int n = 0; n < 16; ++n) {
            uint4 bf;
            asm volatile("ld.shared.v4.b32 {%0,%1,%2,%3}, [%4];"
                         : "=r"(bf.x), "=r"(bf.y), "=r"(bf.z), "=r"(bf.w)
                         : "r"(bBase + (uint32_t)((n * 8 + k) * 512)));
            mma16816(acc[n], ah, bf.x, bf.y);   // hi * hi
            mma16816(acc[n], ah, bf.z, bf.w);   // hi * lo
            mma16816(acc[n], al, bf.x, bf.y);   // lo * hi
        }
    }

    // ---- epilogue: smooth = acc + mean; y_trans = y_obs - smooth ----
    const int ra = row0 + w * 16 + g;
    const int rb = ra + 8;
    const float* meansp = (const float*)(sm + SM_MEANS);
#pragma unroll
    for (int n = 0; n < 16; ++n) {
        const int col = n * 8 + tig * 2;
        const float2 m2 = *(const float2*)(meansp + col);

        float2 sa, sb;
        sa.x = acc[n][0] + m2.x;
        sa.y = acc[n][1] + m2.y;
        sb.x = acc[n][2] + m2.x;
        sb.y = acc[n][3] + m2.y;
        *(float2*)(out + (size_t)ra * CH3 + col) = sa;
        *(float2*)(out + (size_t)rb * CH3 + col) = sb;

        const float2 ya = *(const float2*)(x + (size_t)ra * CH3 + 2 * Ddim + col);
        const float2 yb = *(const float2*)(x + (size_t)rb * CH3 + 2 * Ddim + col);
        float2 ta, tb;
        ta.x = ya.x - sa.x;
        ta.y = ya.y - sa.y;
        tb.x = yb.x - sb.x;
        tb.y = yb.y - sb.y;
        *(float2*)(out + (size_t)ra * CH3 + 2 * Ddim + col) = ta;
        *(float2*)(out + (size_t)rb * CH3 + 2 * Ddim + col) = tb;
    }
}

// ---------------------------------------------------------------------------
extern "C" void kernel_launch(void* const* d_in, const int* in_sizes, int n_in,
                              void* d_out, int out_size) {
    const float* x;
    const float* kmat;
    if (in_sizes[0] == Ddim * Ddim) {
        kmat = (const float*)d_in[0];
        x = (const float*)d_in[1];
    } else {
        x = (const float*)d_in[0];
        kmat = (const float*)d_in[1];
    }
    float* out = (float*)d_out;

    cudaFuncSetAttribute(cci_main, cudaFuncAttributeMaxDynamicSharedMemorySize, SM_TOTAL);

    prep_kernel<<<dim3(Bdim, NCHUNK + 1), Ddim>>>(x, kmat);
    cci_main<<<(Bdim * Tdim) / ROWS_PB, 512, SM_TOTAL>>>(x, out);
}

// round 8
// speedup vs baseline: 2.8525x; 1.2683x over previous
#include <cuda_runtime.h>
#include <cuda_bf16.h>
#include <cstdint>

#define Ddim 128
#define Tdim 1024
#define Bdim 128
#define CH3 (3 * Ddim)
#define NCHUNK 16
#define TCHUNK (Tdim / NCHUNK)
#define ROWS_PB 128
#define NWARPS 8

// ---------------------------------------------------------------------------
// Device globals
// ---------------------------------------------------------------------------
__device__ float g_partial[Bdim * NCHUNK * Ddim];
// Packed E = (K - I) bf16 fragments: [n(16)][k(8)][lane(32)] -> {b0, b1}
__device__ uint2 g_Epk[16 * 8 * 32];

// SMEM layout (per CTA)
#define SM_B     0                                  // 32768 B (E frags)
#define SM_A_HI  32768
#define A_STRIDE 272
#define WARP_A   (16 * A_STRIDE)                    // 4352 B
#define SM_A_LO  (SM_A_HI + NWARPS * WARP_A)        // 67584
#define SM_MEANS (SM_A_LO + NWARPS * WARP_A)        // 102400
#define SM_TOTAL (SM_MEANS + 512)                   // 102912  (2 CTAs/SM)

// ---------------------------------------------------------------------------
__device__ __forceinline__ uint32_t smem_u32(const void* p) {
    uint32_t a;
    asm("{ .reg .u64 t; cvta.to.shared.u64 t, %1; cvt.u32.u64 %0, t; }" : "=r"(a) : "l"(p));
    return a;
}

__device__ __forceinline__ void mma16816(float* d, const uint32_t* a,
                                         uint32_t b0, uint32_t b1) {
    asm volatile(
        "mma.sync.aligned.m16n8k16.row.col.f32.bf16.bf16.f32 "
        "{%0,%1,%2,%3}, {%4,%5,%6,%7}, {%8,%9}, {%0,%1,%2,%3};"
        : "+f"(d[0]), "+f"(d[1]), "+f"(d[2]), "+f"(d[3])
        : "r"(a[0]), "r"(a[1]), "r"(a[2]), "r"(a[3]), "r"(b0), "r"(b1));
}

__device__ __forceinline__ void ldmatrix4(uint32_t* r, uint32_t addr) {
    asm volatile("ldmatrix.sync.aligned.m8n8.x4.shared.b16 {%0,%1,%2,%3}, [%4];"
                 : "=r"(r[0]), "=r"(r[1]), "=r"(r[2]), "=r"(r[3]) : "r"(addr));
}

__device__ __forceinline__ float bf16lo_f(uint32_t u) {
    return __bfloat162float(*(__nv_bfloat16*)&u);
}
__device__ __forceinline__ float bf16hi_f(uint32_t u) {
    uint32_t h = u >> 16;
    return __bfloat162float(*(__nv_bfloat16*)&h);
}

// ---------------------------------------------------------------------------
// Pass 1: mean partials; blocks with y==NCHUNK pack E = K - I fragments.
// ---------------------------------------------------------------------------
__global__ void prep_kernel(const float* __restrict__ x, const float* __restrict__ kmat) {
    if (blockIdx.y == NCHUNK) {
        if (blockIdx.x >= 32) return;
        const int e = blockIdx.x * 128 + threadIdx.x;
        const int n = e >> 8, k = (e >> 5) & 7, lane = e & 31;
        const int g = lane >> 2, tig = lane & 3;
        const int col = n * 8 + g;
        const int r0 = k * 16 + tig * 2;
        const float f00 = kmat[(r0 + 0) * Ddim + col] - ((r0 + 0) == col ? 1.f : 0.f);
        const float f01 = kmat[(r0 + 1) * Ddim + col] - ((r0 + 1) == col ? 1.f : 0.f);
        const float f10 = kmat[(r0 + 8) * Ddim + col] - ((r0 + 8) == col ? 1.f : 0.f);
        const float f11 = kmat[(r0 + 9) * Ddim + col] - ((r0 + 9) == col ? 1.f : 0.f);
        __nv_bfloat162 b0 = __floats2bfloat162_rn(f00, f01);
        __nv_bfloat162 b1 = __floats2bfloat162_rn(f10, f11);
        uint2 v;
        v.x = *(uint32_t*)&b0;
        v.y = *(uint32_t*)&b1;
        g_Epk[e] = v;
        return;
    }
    const int b = blockIdx.x;
    const int c = blockIdx.y;
    const int d = threadIdx.x;
    const float* p = x + ((size_t)b * Tdim + (size_t)c * TCHUNK) * CH3 + d;
    float s[8];
#pragma unroll
    for (int q = 0; q < 8; ++q) s[q] = 0.f;
#pragma unroll 1
    for (int t = 0; t < TCHUNK; t += 8) {
#pragma unroll
        for (int q = 0; q < 8; ++q) s[q] += p[(size_t)(t + q) * CH3];
    }
    float r = ((s[0] + s[1]) + (s[2] + s[3])) + ((s[4] + s[5]) + (s[6] + s[7]));
    g_partial[(b * NCHUNK + c) * Ddim + d] = r;
}

// ---------------------------------------------------------------------------
// Pass 2: per-warp pipeline; GEMM computes only the correction v @ E (1 MMA
// pass, bf16); epilogue re-adds v (hi+lo, fp32-accurate) + mean.
// Block: 256 threads = 8 warps, 128 rows. Grid: 1024. 2 CTAs/SM.
// ---------------------------------------------------------------------------
__global__ void __launch_bounds__(256, 2)
cci_main(const float* __restrict__ x, float* __restrict__ out) {
    extern __shared__ char sm[];
    const uint32_t sbase = smem_u32(sm);

    const int tid = threadIdx.x;
    const int w = tid >> 5;
    const int lane = tid & 31;
    const int g = lane >> 2;
    const int tig = lane & 3;
    const int row0 = blockIdx.x * ROWS_PB;
    const int b = row0 / Tdim;

    // Stage packed E fragments (raw 32KB copy).
    {
        const uint4* src = (const uint4*)g_Epk;
        uint4* dst = (uint4*)(sm + SM_B);
#pragma unroll
        for (int i = tid; i < 2048; i += 256) dst[i] = src[i];
    }

    // Finalize mean for this b.
    if (tid < Ddim) {
        float m = 0.f;
#pragma unroll
        for (int c = 0; c < NCHUNK; ++c) m += g_partial[(b * NCHUNK + c) * Ddim + tid];
        ((float*)(sm + SM_MEANS))[tid] = m * (1.0f / Tdim);
    }
    __syncthreads();   // the ONLY block-wide sync

    const float4 mn = *(const float4*)(sm + SM_MEANS + 16 * lane);

    // ---- prologue: 16 rows/warp in batches of 4 (8 LDG.128 in flight) ----
    char* aHi = sm + SM_A_HI + w * WARP_A;
    char* aLo = sm + SM_A_LO + w * WARP_A;
#pragma unroll
    for (int i0 = 0; i0 < 16; i0 += 4) {
        float4 y[4], wv[4];
#pragma unroll
        for (int q = 0; q < 4; ++q) {
            const float* xr = x + (size_t)(row0 + w * 16 + i0 + q) * CH3;
            y[q]  = *(const float4*)(xr + 4 * lane);
            wv[q] = *(const float4*)(xr + Ddim + 4 * lane);
        }
#pragma unroll
        for (int q = 0; q < 4; ++q) {
            const int i = i0 + q;
            const int row = row0 + w * 16 + i;

            float4 inten;
            inten.x = __expf(wv[q].x);
            inten.y = __expf(wv[q].y);
            inten.z = __expf(wv[q].z);
            inten.w = __expf(wv[q].w);
            *(float4*)(out + (size_t)row * CH3 + Ddim + 4 * lane) = inten;

            float s = (inten.x + inten.y) + (inten.z + inten.w);
#pragma unroll
            for (int off = 16; off; off >>= 1) s += __shfl_xor_sync(0xffffffffu, s, off);
            const float rs = 1.0f / s;

            float4 v;
            v.x = inten.x * rs * (y[q].x - mn.x);
            v.y = inten.y * rs * (y[q].y - mn.y);
            v.z = inten.z * rs * (y[q].z - mn.z);
            v.w = inten.w * rs * (y[q].w - mn.w);

            __nv_bfloat162 h01 = __floats2bfloat162_rn(v.x, v.y);
            __nv_bfloat162 h23 = __floats2bfloat162_rn(v.z, v.w);
            __nv_bfloat162 l01 = __floats2bfloat162_rn(v.x - __bfloat162float(h01.x),
                                                       v.y - __bfloat162float(h01.y));
            __nv_bfloat162 l23 = __floats2bfloat162_rn(v.z - __bfloat162float(h23.x),
                                                       v.w - __bfloat162float(h23.y));
            uint2 ph, pl;
            ph.x = *(uint32_t*)&h01; ph.y = *(uint32_t*)&h23;
            pl.x = *(uint32_t*)&l01; pl.y = *(uint32_t*)&l23;
            *(uint2*)(aHi + i * A_STRIDE + 8 * lane) = ph;
            *(uint2*)(aLo + i * A_STRIDE + 8 * lane) = pl;
        }
    }
    __syncwarp();   // warp-private A tile ready for ldmatrix

    // ---- GEMM: acc = A_hi @ E_hi (single bf16 pass; small correction) ----
    float acc[16][4];
#pragma unroll
    for (int n = 0; n < 16; ++n)
#pragma unroll
        for (int c = 0; c < 4; ++c) acc[n][c] = 0.f;

    const uint32_t aHiAddr =
        sbase + SM_A_HI + w * WARP_A + (lane & 15) * A_STRIDE + (lane >> 4) * 16;
    const uint32_t bBase = sbase + SM_B + lane * 8;

#pragma unroll
    for (int k = 0; k < 8; ++k) {
        uint32_t ah[4];
        ldmatrix4(ah, aHiAddr + k * 32);
#pragma unroll
        for (int n = 0; n < 16; ++n) {
            uint2 bf;
            asm volatile("ld.shared.v2.b32 {%0,%1}, [%2];"
                         : "=r"(bf.x), "=r"(bf.y)
                         : "r"(bBase + (uint32_t)((n * 8 + k) * 256)));
            mma16816(acc[n], ah, bf.x, bf.y);
        }
    }

    // ---- epilogue: smooth = v + acc + mean; y_trans = y_obs - smooth ----
    const int ra = row0 + w * 16 + g;
    const int rb = ra + 8;
    const float* meansp = (const float*)(sm + SM_MEANS);
    const char* aH = aHi;
    const char* aL = aLo;
#pragma unroll
    for (int n = 0; n < 16; ++n) {
        const int col = n * 8 + tig * 2;
        const float2 m2 = *(const float2*)(meansp + col);

        // v (hi+lo) at rows g, g+8 for cols col, col+1
        const uint32_t ha = *(const uint32_t*)(aH + g * A_STRIDE + col * 2);
        const uint32_t la = *(const uint32_t*)(aL + g * A_STRIDE + col * 2);
        const uint32_t hb = *(const uint32_t*)(aH + (g + 8) * A_STRIDE + col * 2);
        const uint32_t lb = *(const uint32_t*)(aL + (g + 8) * A_STRIDE + col * 2);

        float2 sa, sb;
        sa.x = (bf16lo_f(ha) + bf16lo_f(la)) + acc[n][0] + m2.x;
        sa.y = (bf16hi_f(ha) + bf16hi_f(la)) + acc[n][1] + m2.y;
        sb.x = (bf16lo_f(hb) + bf16lo_f(lb)) + acc[n][2] + m2.x;
        sb.y = (bf16hi_f(hb) + bf16hi_f(lb)) + acc[n][3] + m2.y;
        *(float2*)(out + (size_t)ra * CH3 + col) = sa;
        *(float2*)(out + (size_t)rb * CH3 + col) = sb;

        const float2 ya = *(const float2*)(x + (size_t)ra * CH3 + 2 * Ddim + col);
        const float2 yb = *(const float2*)(x + (size_t)rb * CH3 + 2 * Ddim + col);
        float2 ta, tb;
        ta.x = ya.x - sa.x;
        ta.y = ya.y - sa.y;
        tb.x = yb.x - sb.x;
        tb.y = yb.y - sb.y;
        *(float2*)(out + (size_t)ra * CH3 + 2 * Ddim + col) = ta;
        *(float2*)(out + (size_t)rb * CH3 + 2 * Ddim + col) = tb;
    }
}

// ---------------------------------------------------------------------------
extern "C" void kernel_launch(void* const* d_in, const int* in_sizes, int n_in,
                              void* d_out, int out_size) {
    const float* x;
    const float* kmat;
    if (in_sizes[0] == Ddim * Ddim) {
        kmat = (const float*)d_in[0];
        x = (const float*)d_in[1];
    } else {
        x = (const float*)d_in[0];
        kmat = (const float*)d_in[1];
    }
    float* out = (float*)d_out;

    cudaFuncSetAttribute(cci_main, cudaFuncAttributeMaxDynamicSharedMemorySize, SM_TOTAL);

    prep_kernel<<<dim3(Bdim, NCHUNK + 1), Ddim>>>(x, kmat);
    cci_main<<<(Bdim * Tdim) / ROWS_PB, 256, SM_TOTAL>>>(x, out);
}

// round 9
// speedup vs baseline: 3.5332x; 1.2386x over previous
#include <cuda_runtime.h>
#include <cuda_bf16.h>
#include <cstdint>

#define Ddim 128
#define Tdim 1024
#define Bdim 128
#define CH3 (3 * Ddim)
#define NCHUNK 16
#define TCHUNK (Tdim / NCHUNK)
#define ROWS_PB 64
#define NWARPS 8

// ---------------------------------------------------------------------------
// Device globals
// ---------------------------------------------------------------------------
__device__ float g_partial[Bdim * NCHUNK * Ddim];
// Packed E = (K - I) bf16 fragments: [n(16)][k(8)][lane(32)] -> {b0, b1}
__device__ uint2 g_Epk[16 * 8 * 32];

// SMEM layout (per CTA)
#define SM_B     0                                  // 32768 B (E frags)
#define SM_A     32768
#define A_STRIDE 272
#define TILE_A   (16 * A_STRIDE)                    // 4352 B per warp-pair
#define SM_MEANS (SM_A + 4 * TILE_A)                // 50176
#define SM_TOTAL (SM_MEANS + 512)                   // 50688 -> 3+ CTAs/SM

// ---------------------------------------------------------------------------
__device__ __forceinline__ uint32_t smem_u32(const void* p) {
    uint32_t a;
    asm("{ .reg .u64 t; cvta.to.shared.u64 t, %1; cvt.u32.u64 %0, t; }" : "=r"(a) : "l"(p));
    return a;
}

__device__ __forceinline__ void mma16816(float* d, const uint32_t* a,
                                         uint32_t b0, uint32_t b1) {
    asm volatile(
        "mma.sync.aligned.m16n8k16.row.col.f32.bf16.bf16.f32 "
        "{%0,%1,%2,%3}, {%4,%5,%6,%7}, {%8,%9}, {%0,%1,%2,%3};"
        : "+f"(d[0]), "+f"(d[1]), "+f"(d[2]), "+f"(d[3])
        : "r"(a[0]), "r"(a[1]), "r"(a[2]), "r"(a[3]), "r"(b0), "r"(b1));
}

__device__ __forceinline__ void ldmatrix4(uint32_t* r, uint32_t addr) {
    asm volatile("ldmatrix.sync.aligned.m8n8.x4.shared.b16 {%0,%1,%2,%3}, [%4];"
                 : "=r"(r[0]), "=r"(r[1]), "=r"(r[2]), "=r"(r[3]) : "r"(addr));
}

__device__ __forceinline__ float bf16lo_f(uint32_t u) {
    return __bfloat162float(*(__nv_bfloat16*)&u);
}
__device__ __forceinline__ float bf16hi_f(uint32_t u) {
    uint32_t h = u >> 16;
    return __bfloat162float(*(__nv_bfloat16*)&h);
}

// ---------------------------------------------------------------------------
// Pass 1: mean partials; blocks with y==NCHUNK pack E = K - I fragments.
// ---------------------------------------------------------------------------
__global__ void prep_kernel(const float* __restrict__ x, const float* __restrict__ kmat) {
    if (blockIdx.y == NCHUNK) {
        if (blockIdx.x >= 32) return;
        const int e = blockIdx.x * 128 + threadIdx.x;
        const int n = e >> 8, k = (e >> 5) & 7, lane = e & 31;
        const int g = lane >> 2, tig = lane & 3;
        const int col = n * 8 + g;
        const int r0 = k * 16 + tig * 2;
        const float f00 = kmat[(r0 + 0) * Ddim + col] - ((r0 + 0) == col ? 1.f : 0.f);
        const float f01 = kmat[(r0 + 1) * Ddim + col] - ((r0 + 1) == col ? 1.f : 0.f);
        const float f10 = kmat[(r0 + 8) * Ddim + col] - ((r0 + 8) == col ? 1.f : 0.f);
        const float f11 = kmat[(r0 + 9) * Ddim + col] - ((r0 + 9) == col ? 1.f : 0.f);
        __nv_bfloat162 b0 = __floats2bfloat162_rn(f00, f01);
        __nv_bfloat162 b1 = __floats2bfloat162_rn(f10, f11);
        uint2 v;
        v.x = *(uint32_t*)&b0;
        v.y = *(uint32_t*)&b1;
        g_Epk[e] = v;
        return;
    }
    const int b = blockIdx.x;
    const int c = blockIdx.y;
    const int d = threadIdx.x;
    const float* p = x + ((size_t)b * Tdim + (size_t)c * TCHUNK) * CH3 + d;
    float s[8];
#pragma unroll
    for (int q = 0; q < 8; ++q) s[q] = 0.f;
#pragma unroll 1
    for (int t = 0; t < TCHUNK; t += 8) {
#pragma unroll
        for (int q = 0; q < 8; ++q) s[q] += p[(size_t)(t + q) * CH3];
    }
    float r = ((s[0] + s[1]) + (s[2] + s[3])) + ((s[4] + s[5]) + (s[6] + s[7]));
    g_partial[(b * NCHUNK + c) * Ddim + d] = r;
}

// ---------------------------------------------------------------------------
// Pass 2: warp-pair tiles. Each pair of warps shares a 16-row A tile; each
// warp builds 8 rows (prologue) and computes 8 N-fragments (GEMM+epilogue).
// acc = 32 regs/thread -> 3 CTAs/SM. One block sync; pairs sync via named bar.
// ---------------------------------------------------------------------------
__global__ void __launch_bounds__(256, 3)
cci_main(const float* __restrict__ x, float* __restrict__ out) {
    extern __shared__ char sm[];
    const uint32_t sbase = smem_u32(sm);

    const int tid = threadIdx.x;
    const int w = tid >> 5;
    const int lane = tid & 31;
    const int g = lane >> 2;
    const int tig = lane & 3;
    const int pair = w >> 1;
    const int half = w & 1;
    const int row0 = blockIdx.x * ROWS_PB;
    const int b = row0 / Tdim;

    // Stage packed E fragments (raw 32KB copy).
    {
        const uint4* src = (const uint4*)g_Epk;
        uint4* dst = (uint4*)(sm + SM_B);
#pragma unroll
        for (int i = tid; i < 2048; i += 256) dst[i] = src[i];
    }

    // Finalize mean for this b.
    if (tid < Ddim) {
        float m = 0.f;
#pragma unroll
        for (int c = 0; c < NCHUNK; ++c) m += g_partial[(b * NCHUNK + c) * Ddim + tid];
        ((float*)(sm + SM_MEANS))[tid] = m * (1.0f / Tdim);
    }
    __syncthreads();   // the ONLY block-wide sync

    const float4 mn = *(const float4*)(sm + SM_MEANS + 16 * lane);

    // ---- prologue: 8 rows/warp (its half of the pair tile), batches of 4 ----
    char* aHi = sm + SM_A + pair * TILE_A;
#pragma unroll
    for (int i0 = 0; i0 < 8; i0 += 4) {
        float4 y[4], wv[4];
#pragma unroll
        for (int q = 0; q < 4; ++q) {
            const float* xr =
                x + (size_t)(row0 + pair * 16 + half * 8 + i0 + q) * CH3;
            y[q]  = *(const float4*)(xr + 4 * lane);
            wv[q] = *(const float4*)(xr + Ddim + 4 * lane);
        }
#pragma unroll
        for (int q = 0; q < 4; ++q) {
            const int ri = half * 8 + i0 + q;          // row within tile
            const int row = row0 + pair * 16 + ri;

            float4 inten;
            inten.x = __expf(wv[q].x);
            inten.y = __expf(wv[q].y);
            inten.z = __expf(wv[q].z);
            inten.w = __expf(wv[q].w);
            *(float4*)(out + (size_t)row * CH3 + Ddim + 4 * lane) = inten;

            float s = (inten.x + inten.y) + (inten.z + inten.w);
#pragma unroll
            for (int off = 16; off; off >>= 1) s += __shfl_xor_sync(0xffffffffu, s, off);
            const float rs = 1.0f / s;

            float4 v;
            v.x = inten.x * rs * (y[q].x - mn.x);
            v.y = inten.y * rs * (y[q].y - mn.y);
            v.z = inten.z * rs * (y[q].z - mn.z);
            v.w = inten.w * rs * (y[q].w - mn.w);

            __nv_bfloat162 h01 = __floats2bfloat162_rn(v.x, v.y);
            __nv_bfloat162 h23 = __floats2bfloat162_rn(v.z, v.w);
            uint2 ph;
            ph.x = *(uint32_t*)&h01;
            ph.y = *(uint32_t*)&h23;
            *(uint2*)(aHi + ri * A_STRIDE + 8 * lane) = ph;
        }
    }
    // pair barrier: both halves of the tile visible before ldmatrix
    asm volatile("bar.sync %0, 64;" :: "r"(1 + pair) : "memory");

    // ---- GEMM: acc = A_hi @ E (warp covers its 8 N-fragments) ----
    float acc[8][4];
#pragma unroll
    for (int n = 0; n < 8; ++n)
#pragma unroll
        for (int c = 0; c < 4; ++c) acc[n][c] = 0.f;

    const uint32_t aAddr =
        sbase + SM_A + pair * TILE_A + (lane & 15) * A_STRIDE + (lane >> 4) * 16;
    const uint32_t bBase = sbase + SM_B + lane * 8;

#pragma unroll
    for (int k = 0; k < 8; ++k) {
        uint32_t ah[4];
        ldmatrix4(ah, aAddr + k * 32);
#pragma unroll
        for (int n = 0; n < 8; ++n) {
            const int nn = half * 8 + n;
            uint2 bf;
            asm volatile("ld.shared.v2.b32 {%0,%1}, [%2];"
                         : "=r"(bf.x), "=r"(bf.y)
                         : "r"(bBase + (uint32_t)((nn * 8 + k) * 256)));
            mma16816(acc[n], ah, bf.x, bf.y);
        }
    }

    // ---- epilogue: smooth = v + acc + mean; y_trans = y_obs - smooth ----
    const int ra = row0 + pair * 16 + g;
    const int rb = ra + 8;
    const float* meansp = (const float*)(sm + SM_MEANS);
#pragma unroll
    for (int n = 0; n < 8; ++n) {
        const int col = (half * 8 + n) * 8 + tig * 2;
        const float2 m2 = *(const float2*)(meansp + col);

        const uint32_t ha = *(const uint32_t*)(aHi + g * A_STRIDE + col * 2);
        const uint32_t hb = *(const uint32_t*)(aHi + (g + 8) * A_STRIDE + col * 2);

        float2 sa, sb;
        sa.x = bf16lo_f(ha) + acc[n][0] + m2.x;
        sa.y = bf16hi_f(ha) + acc[n][1] + m2.y;
        sb.x = bf16lo_f(hb) + acc[n][2] + m2.x;
        sb.y = bf16hi_f(hb) + acc[n][3] + m2.y;
        *(float2*)(out + (size_t)ra * CH3 + col) = sa;
        *(float2*)(out + (size_t)rb * CH3 + col) = sb;

        const float2 ya = *(const float2*)(x + (size_t)ra * CH3 + 2 * Ddim + col);
        const float2 yb = *(const float2*)(x + (size_t)rb * CH3 + 2 * Ddim + col);
        float2 ta, tb;
        ta.x = ya.x - sa.x;
        ta.y = ya.y - sa.y;
        tb.x = yb.x - sb.x;
        tb.y = yb.y - sb.y;
        *(float2*)(out + (size_t)ra * CH3 + 2 * Ddim + col) = ta;
        *(float2*)(out + (size_t)rb * CH3 + 2 * Ddim + col) = tb;
    }
}

// ---------------------------------------------------------------------------
extern "C" void kernel_launch(void* const* d_in, const int* in_sizes, int n_in,
                              void* d_out, int out_size) {
    const float* x;
    const float* kmat;
    if (in_sizes[0] == Ddim * Ddim) {
        kmat = (const float*)d_in[0];
        x = (const float*)d_in[1];
    } else {
        x = (const float*)d_in[0];
        kmat = (const float*)d_in[1];
    }
    float* out = (float*)d_out;

    cudaFuncSetAttribute(cci_main, cudaFuncAttributeMaxDynamicSharedMemorySize, SM_TOTAL);

    prep_kernel<<<dim3(Bdim, NCHUNK + 1), Ddim>>>(x, kmat);
    cci_main<<<(Bdim * Tdim) / ROWS_PB, 256, SM_TOTAL>>>(x, out);
}